// round 16
// baseline (speedup 1.0000x reference)
#include <cuda_runtime.h>
#include <cuda_fp16.h>
#include <cstdint>

// BahdanauAttention: B=32, SK=8192, D=128  (compute_100-safe: mma.sync fp16 single-pass)
//   logit[b,s] = Wf . tanh(K[b,s] @ W1h + t[b]) + bf   (K2: persistent, fused, 512 thr)
//   e = exp(logit) (unshifted); denom/acc accumulated in K2; V staged via cp.async
//   K4: out[attn] = acc/denom ; out[attn_sm] = e/denom ; self-cleans scratch
// Output layout: [attn (32*128) | attn_sm (32*8192)]

#define B_    32
#define SK_   8192
#define D_    128
#define NTILE 4096          // 64-row tiles (32 b * 128)
#define GRID2 296
#define NTHR  512

// ---------------- scratch (zero-initialized at load; k4 re-zeros each run) ----------------
__device__ float    g_denom[B_];
__device__ float    g_acc[B_ * D_];
__device__ unsigned g_tick;

// ---------------- helpers ----------------
__device__ __forceinline__ uint32_t smem_u32(const void* p) {
    uint32_t r;
    asm("{ .reg .u64 t; cvta.to.shared.u64 t, %1; cvt.u32.u64 %0, t; }" : "=r"(r) : "l"(p));
    return r;
}
__device__ __forceinline__ float ex2f(float x) { float r; asm("ex2.approx.ftz.f32 %0, %1;" : "=f"(r) : "f"(x)); return r; }
__device__ __forceinline__ float tanh_approx(float x) {
    float r; asm("tanh.approx.f32 %0, %1;" : "=f"(r) : "f"(x)); return r;
}
__device__ __forceinline__ uint32_t pack_h2(float x0, float x1) {
    uint32_t r;
    asm("cvt.rn.f16x2.f32 %0, %1, %2;" : "=r"(r) : "f"(x1), "f"(x0));
    return r;
}
__device__ __forceinline__ void ldsm_x4(uint32_t& r0, uint32_t& r1, uint32_t& r2, uint32_t& r3, uint32_t a) {
    asm volatile("ldmatrix.sync.aligned.m8n8.x4.shared.b16 {%0,%1,%2,%3}, [%4];"
                 : "=r"(r0), "=r"(r1), "=r"(r2), "=r"(r3) : "r"(a));
}
__device__ __forceinline__ void ldsm_x4_t(uint32_t& r0, uint32_t& r1, uint32_t& r2, uint32_t& r3, uint32_t a) {
    asm volatile("ldmatrix.sync.aligned.m8n8.x4.trans.shared.b16 {%0,%1,%2,%3}, [%4];"
                 : "=r"(r0), "=r"(r1), "=r"(r2), "=r"(r3) : "r"(a));
}
__device__ __forceinline__ void mma_f16(float* c, uint32_t a0, uint32_t a1, uint32_t a2, uint32_t a3,
                                        uint32_t b0, uint32_t b1) {
    asm volatile("mma.sync.aligned.m16n8k16.row.col.f32.f16.f16.f32 "
                 "{%0,%1,%2,%3}, {%4,%5,%6,%7}, {%8,%9}, {%0,%1,%2,%3};"
                 : "+f"(c[0]), "+f"(c[1]), "+f"(c[2]), "+f"(c[3])
                 : "r"(a0), "r"(a1), "r"(a2), "r"(a3), "r"(b0), "r"(b1));
}
__device__ __forceinline__ void cp_async16(uint32_t saddr, const void* g) {
    asm volatile("cp.async.cg.shared.global [%0], [%1], 16;" :: "r"(saddr), "l"(g));
}
__device__ __forceinline__ void cp_commit() { asm volatile("cp.async.commit_group;" ::: "memory"); }
__device__ __forceinline__ void cp_wait0()  { asm volatile("cp.async.wait_group 0;" ::: "memory"); }

// ---------------- K2: persistent fused GEMM + tanh + Wf dot + softmax-V ----------------
// Tile: 64 rows x 128 n; 512 threads (16 warps): warp = (rowblk rb 0..3 [16 rows], ngrp h 0..3 [32 cols])
#define KSTRIDE  272
#define OFF_T    0
#define OFF_WF   512
#define OFF_PART 1024          // 256 floats (4 n-groups x 64 rows)
#define OFF_E    2048
#define OFF_RED  2304
#define OFF_K    2560
#define OFF_WHI  (OFF_K + 64 * KSTRIDE)       // 19968
#define OFF_V    (OFF_WHI + 128 * KSTRIDE)    // 54784 (V stage: 64 rows x 512B)
#define SMEM_TOT (OFF_V + 64 * 512)           // 87552

__global__ void __launch_bounds__(NTHR, 2) k2_gemm(const float* __restrict__ q,
                                                   const float* __restrict__ kk,
                                                   const float* __restrict__ v,
                                                   const float* __restrict__ W1,
                                                   const float* __restrict__ W2,
                                                   const float* __restrict__ wf,
                                                   const float* __restrict__ bf,
                                                   float* __restrict__ out) {
    extern __shared__ char smem[];
    uint32_t sb = smem_u32(smem);
    int tid = threadIdx.x, wid = tid >> 5, lane = tid & 31;

    const int per = NTILE / GRID2;                 // 13
    const int rem = NTILE - per * GRID2;           // 248
    int c = blockIdx.x;
    int start = c * per + (c < rem ? c : rem);
    int cnt   = per + (c < rem ? 1 : 0);

    float bf0 = bf[0];
    if (tid < 128)      ((float*)(smem + OFF_T))[tid] = 0.f;       // placeholder, overwritten
    if (tid >= 128 && tid < 256) ((float*)(smem + OFF_WF))[tid - 128] = wf[tid - 128];

    // one-time: W1 fp32 -> fp16 into smem
    {
        const float4* w4 = (const float4*)W1;
        #pragma unroll
        for (int i = 0; i < 8; i++) {
            int gid = i * NTHR + tid;              // 0..4095 float4
            int row = gid >> 5, c4 = gid & 31;
            float4 a = w4[gid];
            uint32_t h0 = pack_h2(a.x, a.y);
            uint32_t h1 = pack_h2(a.z, a.w);
            *(uint2*)(smem + OFF_WHI + row * KSTRIDE + c4 * 8) = make_uint2(h0, h1);
        }
    }

    int rb = wid & 3, h = wid >> 2;                // 4 row-blocks x 4 n-groups
    uint32_t a_off = (uint32_t)(rb * 16 + (lane & 15)) * KSTRIDE + (uint32_t)(lane >> 4) * 16;
    uint32_t b_off = (uint32_t)(lane & 15) * KSTRIDE + (uint32_t)h * 64 + (uint32_t)(lane >> 4) * 16;
    const float* t_sm  = (const float*)(smem + OFF_T);
    const float* wf_sm = (const float*)(smem + OFF_WF);
    float* part = (float*)(smem + OFF_PART);
    float* e_sm = (float*)(smem + OFF_E);
    float* red  = (float*)(smem + OFF_RED);
    float* v_sm = (float*)(smem + OFF_V);

    int d_ = tid & 127, g_ = tid >> 7;             // V-accum role: 4 row-groups of 16
    float va0 = 0.f, va1 = 0.f, va2 = 0.f, va3 = 0.f, dacc = 0.f;

    // prefetch first K tile (4 float4/thread)
    float4 pf[4];
    {
        int g0 = start;
        const float4* kg = (const float4*)(kk + ((size_t)(g0 >> 7) * SK_ + (size_t)(g0 & 127) * 64) * 128);
        #pragma unroll
        for (int i = 0; i < 4; i++) pf[i] = kg[i * NTHR + tid];
    }

    int b_cur = -1;
    for (int it = 0; it < cnt; it++) {
        int g = start + it;
        int b = g >> 7, tl = g & 127;

        if (b != b_cur) {
            if (b_cur >= 0) {     // flush previous batch (4 threads per slot: atomic)
                atomicAdd(&g_acc[b_cur * 128 + d_], va0 + va1 + va2 + va3);
                va0 = va1 = va2 = va3 = 0.f;
                if (tid == 0) { atomicAdd(&g_denom[b_cur], dacc); dacc = 0.f; }
            }
            if (tid < 128) {      // t[b] = q[b] @ W2
                float a = 0.f;
                const float* qb = q + b * 128;
                #pragma unroll 8
                for (int d = 0; d < 128; d++) a = fmaf(qb[d], W2[d * 128 + tid], a);
                ((float*)(smem + OFF_T))[tid] = a;
            }
            b_cur = b;
        }

        // prefetched fp32 K tile -> fp16 smem
        #pragma unroll
        for (int i = 0; i < 4; i++) {
            int gid = i * NTHR + tid;
            int row = gid >> 5, c4 = gid & 31;
            uint32_t h0 = pack_h2(pf[i].x, pf[i].y);
            uint32_t h1 = pack_h2(pf[i].z, pf[i].w);
            *(uint2*)(smem + OFF_K + row * KSTRIDE + c4 * 8) = make_uint2(h0, h1);
        }
        __syncthreads();   // sync1

        // stage V tile via cp.async (latency hides under MMA+epilogue)
        {
            const float* vb = v + ((size_t)b * SK_ + (size_t)tl * 64) * 128;
            #pragma unroll
            for (int i = 0; i < 4; i++) {
                int ci = i * NTHR + tid;
                int row = ci >> 5, c16 = ci & 31;
                cp_async16(sb + OFF_V + row * 512 + c16 * 16, vb + (size_t)row * 128 + c16 * 4);
            }
            cp_commit();
        }

        // prefetch next K tile
        if (it + 1 < cnt) {
            int gn = g + 1;
            const float4* kg = (const float4*)(kk + ((size_t)(gn >> 7) * SK_ + (size_t)(gn & 127) * 64) * 128);
            #pragma unroll
            for (int i = 0; i < 4; i++) pf[i] = kg[i * NTHR + tid];
        }

        // ---- MMA: acc = Khalf @ W1h ; warp covers 16 rows x 32 cols ----
        float acc[4][4];
        #pragma unroll
        for (int j = 0; j < 4; j++)
            #pragma unroll
            for (int cc = 0; cc < 4; cc++) acc[j][cc] = 0.f;

        uint32_t abase = sb + OFF_K + a_off;
        uint32_t bbase0 = sb + OFF_WHI + b_off;
        #pragma unroll
        for (int kc = 0; kc < 8; kc++) {
            uint32_t a0, a1, a2, a3;
            ldsm_x4(a0, a1, a2, a3, abase + kc * 32);
            uint32_t bbase = bbase0 + kc * (16 * KSTRIDE);
            #pragma unroll
            for (int j4 = 0; j4 < 2; j4++) {
                uint32_t b0, b1, b2, b3;
                ldsm_x4_t(b0, b1, b2, b3, bbase + j4 * 32);
                mma_f16(acc[2 * j4],     a0, a1, a2, a3, b0, b1);
                mma_f16(acc[2 * j4 + 1], a0, a1, a2, a3, b2, b3);
            }
        }

        // ---- epilogue: dot(tanh.approx(acc + t), wf) over this warp's 32 cols ----
        float slow = 0.f, shigh = 0.f;
        #pragma unroll
        for (int j = 0; j < 4; j++) {
            int c0 = h * 32 + j * 8 + 2 * (lane & 3);
            float t0 = t_sm[c0], t1 = t_sm[c0 + 1];
            float w0 = wf_sm[c0], w1 = wf_sm[c0 + 1];
            slow  = fmaf(tanh_approx(acc[j][0] + t0), w0, slow);
            slow  = fmaf(tanh_approx(acc[j][1] + t1), w1, slow);
            shigh = fmaf(tanh_approx(acc[j][2] + t0), w0, shigh);
            shigh = fmaf(tanh_approx(acc[j][3] + t1), w1, shigh);
        }
        #pragma unroll
        for (int s = 1; s <= 2; s <<= 1) {
            slow  += __shfl_xor_sync(0xffffffffu, slow,  s);
            shigh += __shfl_xor_sync(0xffffffffu, shigh, s);
        }
        if ((lane & 3) == 0) {
            int row = rb * 16 + (lane >> 2);
            part[h * 64 + row]     = slow;
            part[h * 64 + row + 8] = shigh;
        }
        __syncthreads();   // sync2

        // logits -> e (unshifted exp); write unnormalized attn_sm; reduce denom
        if (tid < 64) {
            float logit = part[tid] + part[64 + tid] + part[128 + tid] + part[192 + tid] + bf0;
            float e = ex2f(logit * 1.4426950408889634f);
            e_sm[tid] = e;
            out[4096 + (size_t)b * SK_ + (size_t)tl * 64 + tid] = e;
            float s = e;
            #pragma unroll
            for (int sh = 16; sh > 0; sh >>= 1) s += __shfl_xor_sync(0xffffffffu, s, sh);
            if (lane == 0) red[wid] = s;
        }
        cp_wait0();        // V stage complete (per-thread) before the barrier publishes it
        __syncthreads();   // sync3
        if (tid == 0) dacc += red[0] + red[1];

        // V-weighted accumulation from smem: thread (g_, d_) rows [g_*16, g_*16+16)
        {
            const float* vs = v_sm + (size_t)g_ * 16 * 128 + d_;
            const float* ep = e_sm + g_ * 16;
            #pragma unroll
            for (int r = 0; r < 16; r += 4) {
                va0 = fmaf(ep[r],     vs[(r)     * 128], va0);
                va1 = fmaf(ep[r + 1], vs[(r + 1) * 128], va1);
                va2 = fmaf(ep[r + 2], vs[(r + 2) * 128], va2);
                va3 = fmaf(ep[r + 3], vs[(r + 3) * 128], va3);
            }
        }
        // next iteration's sync1 orders smem reuse
    }
    // final flush
    if (b_cur >= 0) {
        atomicAdd(&g_acc[b_cur * 128 + d_], va0 + va1 + va2 + va3);
        if (tid == 0) atomicAdd(&g_denom[b_cur], dacc);
    }
}

// ---------------- K4: normalize (float4, 2 elems/thread batched for MLP) ----------------
#define K4_GRID 148
__global__ void __launch_bounds__(256) k4_final(float4* __restrict__ out4, int n4) {
    __shared__ int is_last;
    const int stride = K4_GRID * 256;              // 37888
    int i0 = blockIdx.x * 256 + threadIdx.x;
    int i1 = i0 + stride;

    float4 x0, x1;
    float inv0 = 0.f, inv1 = 0.f;
    bool a0 = false;
    if (i0 < n4) {
        if (i0 < 1024) { x0 = ((float4*)g_acc)[i0]; a0 = true; inv0 = 1.0f / g_denom[i0 >> 5]; }
        else           { x0 = out4[i0];             inv0 = 1.0f / g_denom[(i0 - 1024) >> 11]; }
    }
    if (i1 < n4) {
        x1 = out4[i1];
        inv1 = 1.0f / g_denom[(i1 - 1024) >> 11];
    }
    if (i0 < n4) {
        out4[i0] = make_float4(x0.x * inv0, x0.y * inv0, x0.z * inv0, x0.w * inv0);
        if (a0) ((float4*)g_acc)[i0] = make_float4(0.f, 0.f, 0.f, 0.f);
    }
    if (i1 < n4)
        out4[i1] = make_float4(x1.x * inv1, x1.y * inv1, x1.z * inv1, x1.w * inv1);

    __syncthreads();
    if (threadIdx.x == 0) {
        __threadfence();
        unsigned t = atomicAdd(&g_tick, 1);
        is_last = (t == gridDim.x - 1);
    }
    __syncthreads();
    if (is_last) {
        if (threadIdx.x < B_) g_denom[threadIdx.x] = 0.f;
        if (threadIdx.x == 0) { __threadfence(); g_tick = 0; }
    }
}

// ---------------- launch ----------------
extern "C" void kernel_launch(void* const* d_in, const int* in_sizes, int n_in,
                              void* d_out, int out_size) {
    const float* q  = (const float*)d_in[0];
    const float* kk = (const float*)d_in[1];
    const float* v  = (const float*)d_in[2];
    const float* W1 = (const float*)d_in[3];
    const float* W2 = (const float*)d_in[4];
    const float* Wf = (const float*)d_in[5];
    const float* bf = (const float*)d_in[6];
    float* out = (float*)d_out;

    cudaFuncSetAttribute(k2_gemm, cudaFuncAttributeMaxDynamicSharedMemorySize, SMEM_TOT);

    k2_gemm<<<GRID2, NTHR, SMEM_TOT>>>(q, kk, v, W1, W2, Wf, bf, out);
    int n4 = out_size / 4;
    k4_final<<<K4_GRID, 256>>>((float4*)out, n4);
}

// round 17
// speedup vs baseline: 1.2531x; 1.2531x over previous
#include <cuda_runtime.h>
#include <cuda_fp16.h>
#include <cstdint>

// BahdanauAttention: B=32, SK=8192, D=128  (compute_100-safe: mma.sync fp16 single-pass)
//   logit[b,s] = Wf . tanh(K[b,s] @ W1h + t[b]) + bf   (K2: persistent, fused, 256 thr)
//   Warp layout 2rb x 4h (32x32 per warp): B-fragment redundancy 4x -> 2x
//   e = exp(logit) (unshifted); denom/acc accumulated in K2; V staged via cp.async
//   K4: out[attn] = acc/denom ; out[attn_sm] = e/denom ; self-cleans scratch
// Output layout: [attn (32*128) | attn_sm (32*8192)]

#define B_    32
#define SK_   8192
#define D_    128
#define NTILE 4096          // 64-row tiles (32 b * 128)
#define GRID2 296

// ---------------- scratch (zero-initialized at load; k4 re-zeros each run) ----------------
__device__ float    g_denom[B_];
__device__ float    g_acc[B_ * D_];
__device__ unsigned g_tick;

// ---------------- helpers ----------------
__device__ __forceinline__ uint32_t smem_u32(const void* p) {
    uint32_t r;
    asm("{ .reg .u64 t; cvta.to.shared.u64 t, %1; cvt.u32.u64 %0, t; }" : "=r"(r) : "l"(p));
    return r;
}
__device__ __forceinline__ float ex2f(float x) { float r; asm("ex2.approx.ftz.f32 %0, %1;" : "=f"(r) : "f"(x)); return r; }
__device__ __forceinline__ float tanh_approx(float x) {
    float r; asm("tanh.approx.f32 %0, %1;" : "=f"(r) : "f"(x)); return r;
}
__device__ __forceinline__ uint32_t pack_h2(float x0, float x1) {
    uint32_t r;
    asm("cvt.rn.f16x2.f32 %0, %1, %2;" : "=r"(r) : "f"(x1), "f"(x0));
    return r;
}
__device__ __forceinline__ void ldsm_x4(uint32_t& r0, uint32_t& r1, uint32_t& r2, uint32_t& r3, uint32_t a) {
    asm volatile("ldmatrix.sync.aligned.m8n8.x4.shared.b16 {%0,%1,%2,%3}, [%4];"
                 : "=r"(r0), "=r"(r1), "=r"(r2), "=r"(r3) : "r"(a));
}
__device__ __forceinline__ void ldsm_x4_t(uint32_t& r0, uint32_t& r1, uint32_t& r2, uint32_t& r3, uint32_t a) {
    asm volatile("ldmatrix.sync.aligned.m8n8.x4.trans.shared.b16 {%0,%1,%2,%3}, [%4];"
                 : "=r"(r0), "=r"(r1), "=r"(r2), "=r"(r3) : "r"(a));
}
__device__ __forceinline__ void mma_f16(float* c, uint32_t a0, uint32_t a1, uint32_t a2, uint32_t a3,
                                        uint32_t b0, uint32_t b1) {
    asm volatile("mma.sync.aligned.m16n8k16.row.col.f32.f16.f16.f32 "
                 "{%0,%1,%2,%3}, {%4,%5,%6,%7}, {%8,%9}, {%0,%1,%2,%3};"
                 : "+f"(c[0]), "+f"(c[1]), "+f"(c[2]), "+f"(c[3])
                 : "r"(a0), "r"(a1), "r"(a2), "r"(a3), "r"(b0), "r"(b1));
}
__device__ __forceinline__ void cp_async16(uint32_t saddr, const void* g) {
    asm volatile("cp.async.cg.shared.global [%0], [%1], 16;" :: "r"(saddr), "l"(g));
}
__device__ __forceinline__ void cp_commit() { asm volatile("cp.async.commit_group;" ::: "memory"); }
__device__ __forceinline__ void cp_wait0()  { asm volatile("cp.async.wait_group 0;" ::: "memory"); }

// ---------------- K2: persistent fused GEMM + tanh + Wf dot + softmax-V ----------------
// Tile: 64 rows x 128 n; 256 threads (8 warps): warp = (rowblk rb 0..1 [32 rows], ngrp h 0..3 [32 cols])
#define KSTRIDE  272
#define OFF_T    0
#define OFF_WF   512
#define OFF_PART 1024          // 256 floats (4 n-groups x 64 rows)
#define OFF_E    2048
#define OFF_RED  2304
#define OFF_K    2560
#define OFF_WHI  (OFF_K + 64 * KSTRIDE)       // 19968
#define OFF_V    (OFF_WHI + 128 * KSTRIDE)    // 54784 (V stage: 64 rows x 512B)
#define SMEM_TOT (OFF_V + 64 * 512)           // 87552

__global__ void __launch_bounds__(256, 2) k2_gemm(const float* __restrict__ q,
                                                  const float* __restrict__ kk,
                                                  const float* __restrict__ v,
                                                  const float* __restrict__ W1,
                                                  const float* __restrict__ W2,
                                                  const float* __restrict__ wf,
                                                  const float* __restrict__ bf,
                                                  float* __restrict__ out) {
    extern __shared__ char smem[];
    uint32_t sb = smem_u32(smem);
    int tid = threadIdx.x, wid = tid >> 5, lane = tid & 31;

    const int per = NTILE / GRID2;                 // 13
    const int rem = NTILE - per * GRID2;           // 248
    int c = blockIdx.x;
    int start = c * per + (c < rem ? c : rem);
    int cnt   = per + (c < rem ? 1 : 0);

    float bf0 = bf[0];
    if (tid >= 128) ((float*)(smem + OFF_WF))[tid - 128] = wf[tid - 128];

    // one-time: W1 fp32 -> fp16 into smem
    {
        const float4* w4 = (const float4*)W1;
        #pragma unroll
        for (int i = 0; i < 16; i++) {
            int gid = i * 256 + tid;               // 0..4095 float4
            int row = gid >> 5, c4 = gid & 31;
            float4 a = w4[gid];
            uint32_t h0 = pack_h2(a.x, a.y);
            uint32_t h1 = pack_h2(a.z, a.w);
            *(uint2*)(smem + OFF_WHI + row * KSTRIDE + c4 * 8) = make_uint2(h0, h1);
        }
    }

    int rb = wid & 1, h = wid >> 1;                // 2 row-blocks (32 rows) x 4 n-groups (32 cols)
    // A fragments: two 16-row halves of this warp's 32 rows
    uint32_t a_off0 = (uint32_t)(rb * 32 + (lane & 15)) * KSTRIDE + (uint32_t)(lane >> 4) * 16;
    uint32_t a_off1 = a_off0 + 16 * KSTRIDE;
    // B fragments: this warp's 32 cols (h*64 bytes), two 16-col halves (j4*32 bytes)
    uint32_t b_off = (uint32_t)(lane & 15) * KSTRIDE + (uint32_t)h * 64 + (uint32_t)(lane >> 4) * 16;
    const float* t_sm  = (const float*)(smem + OFF_T);
    const float* wf_sm = (const float*)(smem + OFF_WF);
    float* part = (float*)(smem + OFF_PART);
    float* e_sm = (float*)(smem + OFF_E);
    float* red  = (float*)(smem + OFF_RED);
    float* v_sm = (float*)(smem + OFF_V);

    int d_ = tid & 127, g_ = tid >> 7;             // V-accum role
    float va0 = 0.f, va1 = 0.f, va2 = 0.f, va3 = 0.f, dacc = 0.f;

    // prefetch first K tile
    float4 pf[8];
    {
        int g0 = start;
        const float4* kg = (const float4*)(kk + ((size_t)(g0 >> 7) * SK_ + (size_t)(g0 & 127) * 64) * 128);
        #pragma unroll
        for (int i = 0; i < 8; i++) pf[i] = kg[i * 256 + tid];
    }

    int b_cur = -1;
    for (int it = 0; it < cnt; it++) {
        int g = start + it;
        int b = g >> 7, tl = g & 127;

        if (b != b_cur) {
            if (b_cur >= 0) {     // flush previous batch
                atomicAdd(&g_acc[b_cur * 128 + d_], va0 + va1 + va2 + va3);
                va0 = va1 = va2 = va3 = 0.f;
                if (tid == 0) { atomicAdd(&g_denom[b_cur], dacc); dacc = 0.f; }
            }
            if (tid < 128) {      // t[b] = q[b] @ W2
                float a = 0.f;
                const float* qb = q + b * 128;
                #pragma unroll 8
                for (int d = 0; d < 128; d++) a = fmaf(qb[d], W2[d * 128 + tid], a);
                ((float*)(smem + OFF_T))[tid] = a;
            }
            b_cur = b;
        }

        // prefetched fp32 K tile -> fp16 smem
        #pragma unroll
        for (int i = 0; i < 8; i++) {
            int gid = i * 256 + tid;
            int row = gid >> 5, c4 = gid & 31;
            uint32_t h0 = pack_h2(pf[i].x, pf[i].y);
            uint32_t h1 = pack_h2(pf[i].z, pf[i].w);
            *(uint2*)(smem + OFF_K + row * KSTRIDE + c4 * 8) = make_uint2(h0, h1);
        }
        __syncthreads();   // sync1

        // stage V tile via cp.async (latency hides under MMA+epilogue)
        {
            const float* vb = v + ((size_t)b * SK_ + (size_t)tl * 64) * 128;
            #pragma unroll
            for (int i = 0; i < 8; i++) {
                int ci = i * 256 + tid;
                int row = ci >> 5, c16 = ci & 31;
                cp_async16(sb + OFF_V + row * 512 + c16 * 16, vb + (size_t)row * 128 + c16 * 4);
            }
            cp_commit();
        }

        // prefetch next K tile
        if (it + 1 < cnt) {
            int gn = g + 1;
            const float4* kg = (const float4*)(kk + ((size_t)(gn >> 7) * SK_ + (size_t)(gn & 127) * 64) * 128);
            #pragma unroll
            for (int i = 0; i < 8; i++) pf[i] = kg[i * 256 + tid];
        }

        // ---- MMA: acc = Khalf @ W1h ; warp covers 32 rows x 32 cols ----
        // acc[r16*4 + j8][4]: r16 = 16-row half, j8 = n8 group within 32 cols
        float acc[8][4];
        #pragma unroll
        for (int j = 0; j < 8; j++)
            #pragma unroll
            for (int cc = 0; cc < 4; cc++) acc[j][cc] = 0.f;

        uint32_t abase0 = sb + OFF_K + a_off0;
        uint32_t abase1 = sb + OFF_K + a_off1;
        uint32_t bbase0 = sb + OFF_WHI + b_off;
        #pragma unroll
        for (int kc = 0; kc < 8; kc++) {
            uint32_t a00, a01, a02, a03, a10, a11, a12, a13;
            ldsm_x4(a00, a01, a02, a03, abase0 + kc * 32);
            ldsm_x4(a10, a11, a12, a13, abase1 + kc * 32);
            uint32_t bbase = bbase0 + kc * (16 * KSTRIDE);
            #pragma unroll
            for (int j4 = 0; j4 < 2; j4++) {
                uint32_t b0, b1, b2, b3;
                ldsm_x4_t(b0, b1, b2, b3, bbase + j4 * 32);
                mma_f16(acc[2 * j4],     a00, a01, a02, a03, b0, b1);
                mma_f16(acc[2 * j4 + 1], a00, a01, a02, a03, b2, b3);
                mma_f16(acc[4 + 2 * j4],     a10, a11, a12, a13, b0, b1);
                mma_f16(acc[4 + 2 * j4 + 1], a10, a11, a12, a13, b2, b3);
            }
        }

        // ---- epilogue: dot(tanh.approx(acc + t), wf) over this warp's 32 cols ----
        // 4 row-sums: (r16, low/high 8-row half)
        float s00 = 0.f, s01 = 0.f, s10 = 0.f, s11 = 0.f;
        #pragma unroll
        for (int j8 = 0; j8 < 4; j8++) {
            int c0 = h * 32 + j8 * 8 + 2 * (lane & 3);
            float t0 = t_sm[c0], t1 = t_sm[c0 + 1];
            float w0 = wf_sm[c0], w1 = wf_sm[c0 + 1];
            s00 = fmaf(tanh_approx(acc[j8][0] + t0), w0, s00);
            s00 = fmaf(tanh_approx(acc[j8][1] + t1), w1, s00);
            s01 = fmaf(tanh_approx(acc[j8][2] + t0), w0, s01);
            s01 = fmaf(tanh_approx(acc[j8][3] + t1), w1, s01);
            s10 = fmaf(tanh_approx(acc[4 + j8][0] + t0), w0, s10);
            s10 = fmaf(tanh_approx(acc[4 + j8][1] + t1), w1, s10);
            s11 = fmaf(tanh_approx(acc[4 + j8][2] + t0), w0, s11);
            s11 = fmaf(tanh_approx(acc[4 + j8][3] + t1), w1, s11);
        }
        #pragma unroll
        for (int s = 1; s <= 2; s <<= 1) {
            s00 += __shfl_xor_sync(0xffffffffu, s00, s);
            s01 += __shfl_xor_sync(0xffffffffu, s01, s);
            s10 += __shfl_xor_sync(0xffffffffu, s10, s);
            s11 += __shfl_xor_sync(0xffffffffu, s11, s);
        }
        if ((lane & 3) == 0) {
            int r0 = rb * 32 + (lane >> 2);
            part[h * 64 + r0]      = s00;   // r16=0 rows 0..7
            part[h * 64 + r0 + 8]  = s01;   // r16=0 rows 8..15
            part[h * 64 + r0 + 16] = s10;   // r16=1 rows 16..23
            part[h * 64 + r0 + 24] = s11;   // r16=1 rows 24..31
        }
        __syncthreads();   // sync2

        // logits -> e (unshifted exp); write unnormalized attn_sm; reduce denom
        if (tid < 64) {
            float logit = part[tid] + part[64 + tid] + part[128 + tid] + part[192 + tid] + bf0;
            float e = ex2f(logit * 1.4426950408889634f);
            e_sm[tid] = e;
            out[4096 + (size_t)b * SK_ + (size_t)tl * 64 + tid] = e;
            float s = e;
            #pragma unroll
            for (int sh = 16; sh > 0; sh >>= 1) s += __shfl_xor_sync(0xffffffffu, s, sh);
            if (lane == 0) red[wid] = s;
        }
        cp_wait0();        // V stage complete (per-thread) before the barrier publishes it
        __syncthreads();   // sync3
        if (tid == 0) dacc += red[0] + red[1];

        // V-weighted accumulation from smem: thread (g_, d_) rows [g_*32, g_*32+32)
        {
            const float* vs = v_sm + (size_t)g_ * 32 * 128 + d_;
            const float* ep = e_sm + g_ * 32;
            #pragma unroll
            for (int r = 0; r < 32; r += 4) {
                va0 = fmaf(ep[r],     vs[(r)     * 128], va0);
                va1 = fmaf(ep[r + 1], vs[(r + 1) * 128], va1);
                va2 = fmaf(ep[r + 2], vs[(r + 2) * 128], va2);
                va3 = fmaf(ep[r + 3], vs[(r + 3) * 128], va3);
            }
        }
        // next iteration's sync1 orders smem reuse
    }
    // final flush
    if (b_cur >= 0) {
        atomicAdd(&g_acc[b_cur * 128 + d_], va0 + va1 + va2 + va3);
        if (tid == 0) atomicAdd(&g_denom[b_cur], dacc);
    }
}

// ---------------- K4: normalize (float4, 2 elems/thread batched for MLP) ----------------
#define K4_GRID 148
__global__ void __launch_bounds__(256) k4_final(float4* __restrict__ out4, int n4) {
    __shared__ int is_last;
    const int stride = K4_GRID * 256;              // 37888
    int i0 = blockIdx.x * 256 + threadIdx.x;
    int i1 = i0 + stride;

    float4 x0, x1;
    float inv0 = 0.f, inv1 = 0.f;
    bool a0 = false;
    if (i0 < n4) {
        if (i0 < 1024) { x0 = ((float4*)g_acc)[i0]; a0 = true; inv0 = 1.0f / g_denom[i0 >> 5]; }
        else           { x0 = out4[i0];             inv0 = 1.0f / g_denom[(i0 - 1024) >> 11]; }
    }
    if (i1 < n4) {
        x1 = out4[i1];
        inv1 = 1.0f / g_denom[(i1 - 1024) >> 11];
    }
    if (i0 < n4) {
        out4[i0] = make_float4(x0.x * inv0, x0.y * inv0, x0.z * inv0, x0.w * inv0);
        if (a0) ((float4*)g_acc)[i0] = make_float4(0.f, 0.f, 0.f, 0.f);
    }
    if (i1 < n4)
        out4[i1] = make_float4(x1.x * inv1, x1.y * inv1, x1.z * inv1, x1.w * inv1);

    __syncthreads();
    if (threadIdx.x == 0) {
        __threadfence();
        unsigned t = atomicAdd(&g_tick, 1);
        is_last = (t == gridDim.x - 1);
    }
    __syncthreads();
    if (is_last) {
        if (threadIdx.x < B_) g_denom[threadIdx.x] = 0.f;
        if (threadIdx.x == 0) { __threadfence(); g_tick = 0; }
    }
}

// ---------------- launch ----------------
extern "C" void kernel_launch(void* const* d_in, const int* in_sizes, int n_in,
                              void* d_out, int out_size) {
    const float* q  = (const float*)d_in[0];
    const float* kk = (const float*)d_in[1];
    const float* v  = (const float*)d_in[2];
    const float* W1 = (const float*)d_in[3];
    const float* W2 = (const float*)d_in[4];
    const float* Wf = (const float*)d_in[5];
    const float* bf = (const float*)d_in[6];
    float* out = (float*)d_out;

    cudaFuncSetAttribute(k2_gemm, cudaFuncAttributeMaxDynamicSharedMemorySize, SMEM_TOT);

    k2_gemm<<<GRID2, 256, SMEM_TOT>>>(q, kk, v, W1, W2, Wf, bf, out);
    int n4 = out_size / 4;
    k4_final<<<K4_GRID, 256>>>((float4*)out, n4);
}